// round 4
// baseline (speedup 1.0000x reference)
#include <cuda_runtime.h>
#include <cuda_bf16.h>
#include <cstdint>

#define DD 64

#define MAX_E_TOTAL 2000000      // E_KG + E_UI
#define MAX_SEG     160000       // N_ENT + N_USR
#define MAX_ENT     100000
#define MAX_REL     16

// -------- device scratch (no allocations allowed) --------
static __device__ float g_score[MAX_E_TOTAL];          // ex = exp(score)
static __device__ float g_ssum [MAX_SEG];
static __device__ float g_S    [MAX_ENT * MAX_REL];    // precomputed ent . rel

__device__ __forceinline__ void red_add_v4(float* p, float4 v) {
    asm volatile("red.global.add.v4.f32 [%0], {%1,%2,%3,%4};"
                 :: "l"(p), "f"(v.x), "f"(v.y), "f"(v.z), "f"(v.w) : "memory");
}
__device__ __forceinline__ float dot4(float4 a, float4 b) {
    return a.x * b.x + a.y * b.y + a.z * b.z + a.w * b.w;
}
__device__ __forceinline__ float dot4x3(float4 a, float4 b, float4 c) {
    return a.x * b.x * c.x + a.y * b.y * c.y + a.z * b.z * c.z + a.w * b.w * c.w;
}

// ---------------------------------------------------------------------------
// K0: prep — three disjoint ranges in one grid:
//   [0, n4)                 : zero agg output (float4)
//   [n4, n4+n_seg)          : zero ssum
//   [n4+n_seg, +N_ENT*8)    : compute S[ent][r] = ent_row . rel_row  (8 lanes/ent)
// rel_emb staged in smem (4KB).
// ---------------------------------------------------------------------------
__global__ void k_prep(const float4* __restrict__ ent4,
                       const float4* __restrict__ rel4,
                       float4* __restrict__ out4,
                       int n4, int n_seg, int N_ENT, int N_REL)
{
    __shared__ float4 s_rel[MAX_REL * 16];
    for (int j = threadIdx.x; j < N_REL * 16; j += blockDim.x)
        s_rel[j] = rel4[j];

    int i = blockIdx.x * blockDim.x + threadIdx.x;

    if (i < n4) {
        out4[i] = make_float4(0.f, 0.f, 0.f, 0.f);
        return;
    }
    if (i < n4 + n_seg) {
        g_ssum[i - n4] = 0.0f;
        return;
    }
    __syncthreads();   // only S-range blocks reach here... (see note below)

    int j = i - (n4 + n_seg);
    int ent = j >> 3;
    int c   = j & 7;
    if (ent >= N_ENT) return;

    float4 ev0 = ent4[(long long)ent * 16 + c];
    float4 ev1 = ent4[(long long)ent * 16 + c + 8];

    float vals[MAX_REL];
    #pragma unroll
    for (int r = 0; r < MAX_REL; r++) {
        float p = dot4(ev0, s_rel[r * 16 + c]) + dot4(ev1, s_rel[r * 16 + c + 8]);
        #pragma unroll
        for (int o = 4; o > 0; o >>= 1)
            p += __shfl_xor_sync(0xffffffffu, p, o);
        vals[r] = p;
    }
    // each lane writes 2 of the 16 values (all lanes hold all sums)
    g_S[(long long)ent * MAX_REL + c]     = vals[c];
    g_S[(long long)ent * MAX_REL + c + 8] = vals[c + 8];
}

// ---------------------------------------------------------------------------
// K1: FUSED heavy pass. 8 threads per edge, 2x float4 per thread.
//   KG: score via precomputed S lookup (no rel loads, no dot, no shfl)
//   UI: triple dot with inter row staged in smem
// ---------------------------------------------------------------------------
__global__ void k_fused(const float4* __restrict__ ent4,
                        const float4* __restrict__ usr4,
                        const float4* __restrict__ inter4,
                        const int* __restrict__ eidx,      // [2, E_KG]
                        const int* __restrict__ etype,     // [E_KG]
                        const int* __restrict__ uidx,      // [E_UI]
                        const int* __restrict__ iidx,      // [E_UI]
                        const int* __restrict__ itype,     // [E_UI]
                        float* __restrict__ out,
                        int E_KG, int E_UI, int N_ENT, int N_USR, int N_ITYPE)
{
    __shared__ float4 s_inter[8 * 16];
    for (int j = threadIdx.x; j < N_ITYPE * 16; j += blockDim.x)
        s_inter[j] = inter4[j];
    __syncthreads();

    long long tid = (long long)blockIdx.x * blockDim.x + threadIdx.x;
    int e = (int)(tid >> 3);
    int c = (int)(tid & 7);
    int T = E_KG + E_UI;
    if (e >= T) return;

    float* ent_agg = out;
    float* usr_agg = out + (long long)N_ENT * DD;

    if (e < E_KG) {
        int head = eidx[e];
        int tail = eidx[E_KG + e];
        int rt   = etype[e] - 1;
        float sc = g_S[(long long)tail * MAX_REL + rt];   // broadcast within group
        float ex = __expf(sc * 0.125f);
        const float4* nrow = ent4 + (long long)tail * 16;
        float4 nv0 = nrow[c];
        float4 nv1 = nrow[c + 8];
        float* dst = ent_agg + (long long)head * DD;
        red_add_v4(dst + c * 4,
                   make_float4(nv0.x * ex, nv0.y * ex, nv0.z * ex, nv0.w * ex));
        red_add_v4(dst + (c + 8) * 4,
                   make_float4(nv1.x * ex, nv1.y * ex, nv1.z * ex, nv1.w * ex));
        if (c == 0) {
            g_score[e] = ex;
            atomicAdd(&g_ssum[head], ex);
        }
    } else {
        int i  = e - E_KG;
        int u  = uidx[i];
        int it = iidx[i];
        int ty = itype[i];
        const float4* irow = ent4 + (long long)it * 16;
        const float4* urow = usr4 + (long long)u * 16;
        float4 iv0 = irow[c];
        float4 iv1 = irow[c + 8];
        float4 uv0 = urow[c];
        float4 uv1 = urow[c + 8];
        float4 tv0 = s_inter[ty * 16 + c];
        float4 tv1 = s_inter[ty * 16 + c + 8];
        float p = dot4x3(iv0, uv0, tv0) + dot4x3(iv1, uv1, tv1);
        #pragma unroll
        for (int o = 4; o > 0; o >>= 1)
            p += __shfl_xor_sync(0xffffffffu, p, o);
        float ex = __expf(p);
        float* dst = usr_agg + (long long)u * DD;
        red_add_v4(dst + c * 4,
                   make_float4(iv0.x * ex, iv0.y * ex, iv0.z * ex, iv0.w * ex));
        red_add_v4(dst + (c + 8) * 4,
                   make_float4(iv1.x * ex, iv1.y * ex, iv1.z * ex, iv1.w * ex));
        if (c == 0) {
            g_score[e] = ex;
            atomicAdd(&g_ssum[N_ENT + u], ex);
        }
    }
}

// ---------------------------------------------------------------------------
// K2: merged tail. [0, n4): normalize agg rows; [n4, n4+T): edge weights.
// ---------------------------------------------------------------------------
__global__ void k_tail(float4* __restrict__ out4, int n4,
                       const int* __restrict__ eidx,
                       const int* __restrict__ uidx,
                       float* __restrict__ out,
                       int E_KG, int E_UI, int N_ENT, int N_USR)
{
    int i = blockIdx.x * blockDim.x + threadIdx.x;
    if (i < n4) {
        int seg = i >> 4;
        float s = g_ssum[seg];
        float inv = (s > 0.0f) ? (1.0f / s) : 0.0f;
        float4 v = out4[i];
        v.x *= inv; v.y *= inv; v.z *= inv; v.w *= inv;
        out4[i] = v;
    } else {
        int e = i - n4;
        int T = E_KG + E_UI;
        if (e >= T) return;
        float* att_out = out + (long long)(N_ENT + N_USR) * DD;
        float* w1_out  = att_out + E_UI;
        if (e < E_KG) {
            int head = eidx[e];
            w1_out[e] = g_score[e] / g_ssum[head];
        } else {
            int j = e - E_KG;
            int u = uidx[j];
            att_out[j] = g_score[e] / g_ssum[N_ENT + u];
        }
    }
}

// ---------------------------------------------------------------------------
extern "C" void kernel_launch(void* const* d_in, const int* in_sizes, int n_in,
                              void* d_out, int out_size)
{
    const float4* ent4   = (const float4*)d_in[0];
    const float4* usr4   = (const float4*)d_in[1];
    const float4* inter4 = (const float4*)d_in[2];
    const float4* rel4   = (const float4*)d_in[3];
    const int* eidx  = (const int*)d_in[4];
    const int* etype = (const int*)d_in[5];
    const int* uidx  = (const int*)d_in[6];
    const int* iidx  = (const int*)d_in[7];
    const int* itype = (const int*)d_in[8];
    float* out = (float*)d_out;

    int N_ENT   = in_sizes[0] / DD;
    int N_USR   = in_sizes[1] / DD;
    int N_ITYPE = in_sizes[2] / DD;
    int N_REL   = in_sizes[3] / DD;
    int E_KG    = in_sizes[5];
    int E_UI    = in_sizes[6];
    int T = E_KG + E_UI;
    int n_agg = (N_ENT + N_USR) * DD;
    int n_seg = N_ENT + N_USR;
    int n4 = n_agg / 4;

    const int B = 256;

    int prep_work = n4 + n_seg + N_ENT * 8;
    k_prep<<<(prep_work + B - 1) / B, B>>>(ent4, rel4, (float4*)out,
                                           n4, n_seg, N_ENT, N_REL);

    long long wide = (long long)T * 8;
    int g_wide = (int)((wide + B - 1) / B);
    k_fused<<<g_wide, B>>>(ent4, usr4, inter4,
                           eidx, etype, uidx, iidx, itype,
                           out, E_KG, E_UI, N_ENT, N_USR, N_ITYPE);

    int tail_work = n4 + T;
    k_tail<<<(tail_work + B - 1) / B, B>>>((float4*)out, n4, eidx, uidx, out,
                                           E_KG, E_UI, N_ENT, N_USR);
}

// round 5
// speedup vs baseline: 1.0110x; 1.0110x over previous
#include <cuda_runtime.h>
#include <cuda_bf16.h>
#include <cstdint>

#define DD 64

#define MAX_E_TOTAL 2000000      // E_KG + E_UI
#define MAX_SEG     160000       // N_ENT + N_USR

// -------- device scratch (no allocations allowed) --------
static __device__ float g_score[MAX_E_TOTAL];   // holds ex = exp(score)
static __device__ float g_ssum [MAX_SEG];

__device__ __forceinline__ void red_add_v4(float* p, float4 v) {
    asm volatile("red.global.add.v4.f32 [%0], {%1,%2,%3,%4};"
                 :: "l"(p), "f"(v.x), "f"(v.y), "f"(v.z), "f"(v.w) : "memory");
}
__device__ __forceinline__ float dot4(float4 a, float4 b) {
    return a.x * b.x + a.y * b.y + a.z * b.z + a.w * b.w;
}
__device__ __forceinline__ float dot4x3(float4 a, float4 b, float4 c) {
    return a.x * b.x * c.x + a.y * b.y * c.y + a.z * b.z * c.z + a.w * b.w * c.w;
}

// ---------------------------------------------------------------------------
// K0: init — zero agg outputs (float4) and segment sums
// ---------------------------------------------------------------------------
__global__ void k_init(float4* out4, int n4, int n_seg) {
    int i = blockIdx.x * blockDim.x + threadIdx.x;
    int stride = gridDim.x * blockDim.x;
    float4 z = make_float4(0.f, 0.f, 0.f, 0.f);
    for (int j = i; j < n4; j += stride) out4[j] = z;
    for (int j = i; j < n_seg; j += stride) g_ssum[j] = 0.0f;
}

// ---------------------------------------------------------------------------
// K1: FUSED heavy pass. 4 threads per edge, 4x float4 per thread.
//   gather -> dot (2-step shfl) -> ex=exp(s) -> red.v4 of ex*row -> ssum atomic
//   (softmax is shift-invariant; scores are O(0.1), so no max pass needed)
// ---------------------------------------------------------------------------
__global__ void __launch_bounds__(256)
k_fused(const float4* __restrict__ ent4,
        const float4* __restrict__ usr4,
        const float4* __restrict__ inter4,
        const float4* __restrict__ rel4,
        const int* __restrict__ eidx,      // [2, E_KG]
        const int* __restrict__ etype,     // [E_KG]
        const int* __restrict__ uidx,      // [E_UI]
        const int* __restrict__ iidx,      // [E_UI]
        const int* __restrict__ itype,     // [E_UI]
        float* __restrict__ out,
        int E_KG, int E_UI, int N_ENT, int N_USR)
{
    long long tid = (long long)blockIdx.x * blockDim.x + threadIdx.x;
    int e = (int)(tid >> 2);
    int c = (int)(tid & 3);          // lane-group offset: quads c, c+4, c+8, c+12
    int T = E_KG + E_UI;
    if (e >= T) return;

    float* ent_agg = out;
    float* usr_agg = out + (long long)N_ENT * DD;

    if (e < E_KG) {
        int head = eidx[e];
        int tail = eidx[E_KG + e];
        int rt   = etype[e] - 1;
        const float4* nrow = ent4 + (long long)tail * 16;
        const float4* rrow = rel4 + rt * 16;
        float4 nv0 = nrow[c];
        float4 nv1 = nrow[c + 4];
        float4 nv2 = nrow[c + 8];
        float4 nv3 = nrow[c + 12];
        float4 rv0 = rrow[c];
        float4 rv1 = rrow[c + 4];
        float4 rv2 = rrow[c + 8];
        float4 rv3 = rrow[c + 12];
        float p = dot4(nv0, rv0) + dot4(nv1, rv1) + dot4(nv2, rv2) + dot4(nv3, rv3);
        p += __shfl_xor_sync(0xffffffffu, p, 2);
        p += __shfl_xor_sync(0xffffffffu, p, 1);
        float ex = __expf(p * 0.125f);
        float* dst = ent_agg + (long long)head * DD;
        red_add_v4(dst + c * 4,
                   make_float4(nv0.x * ex, nv0.y * ex, nv0.z * ex, nv0.w * ex));
        red_add_v4(dst + (c + 4) * 4,
                   make_float4(nv1.x * ex, nv1.y * ex, nv1.z * ex, nv1.w * ex));
        red_add_v4(dst + (c + 8) * 4,
                   make_float4(nv2.x * ex, nv2.y * ex, nv2.z * ex, nv2.w * ex));
        red_add_v4(dst + (c + 12) * 4,
                   make_float4(nv3.x * ex, nv3.y * ex, nv3.z * ex, nv3.w * ex));
        if (c == 0) {
            g_score[e] = ex;
            atomicAdd(&g_ssum[head], ex);
        }
    } else {
        int i  = e - E_KG;
        int u  = uidx[i];
        int it = iidx[i];
        int ty = itype[i];
        const float4* irow = ent4 + (long long)it * 16;
        const float4* urow = usr4 + (long long)u * 16;
        const float4* trow = inter4 + ty * 16;
        float4 iv0 = irow[c];
        float4 iv1 = irow[c + 4];
        float4 iv2 = irow[c + 8];
        float4 iv3 = irow[c + 12];
        float4 uv0 = urow[c];
        float4 uv1 = urow[c + 4];
        float4 uv2 = urow[c + 8];
        float4 uv3 = urow[c + 12];
        float4 tv0 = trow[c];
        float4 tv1 = trow[c + 4];
        float4 tv2 = trow[c + 8];
        float4 tv3 = trow[c + 12];
        float p = dot4x3(iv0, uv0, tv0) + dot4x3(iv1, uv1, tv1)
                + dot4x3(iv2, uv2, tv2) + dot4x3(iv3, uv3, tv3);
        p += __shfl_xor_sync(0xffffffffu, p, 2);
        p += __shfl_xor_sync(0xffffffffu, p, 1);
        float ex = __expf(p);
        float* dst = usr_agg + (long long)u * DD;
        red_add_v4(dst + c * 4,
                   make_float4(iv0.x * ex, iv0.y * ex, iv0.z * ex, iv0.w * ex));
        red_add_v4(dst + (c + 4) * 4,
                   make_float4(iv1.x * ex, iv1.y * ex, iv1.z * ex, iv1.w * ex));
        red_add_v4(dst + (c + 8) * 4,
                   make_float4(iv2.x * ex, iv2.y * ex, iv2.z * ex, iv2.w * ex));
        red_add_v4(dst + (c + 12) * 4,
                   make_float4(iv3.x * ex, iv3.y * ex, iv3.z * ex, iv3.w * ex));
        if (c == 0) {
            g_score[e] = ex;
            atomicAdd(&g_ssum[N_ENT + u], ex);
        }
    }
}

// ---------------------------------------------------------------------------
// K2: merged tail. [0, n4): normalize agg rows; [n4, n4+T): edge weights.
// ---------------------------------------------------------------------------
__global__ void k_tail(float4* __restrict__ out4, int n4,
                       const int* __restrict__ eidx,
                       const int* __restrict__ uidx,
                       float* __restrict__ out,
                       int E_KG, int E_UI, int N_ENT, int N_USR)
{
    int i = blockIdx.x * blockDim.x + threadIdx.x;
    if (i < n4) {
        int seg = i >> 4;
        float s = g_ssum[seg];
        float inv = (s > 0.0f) ? __frcp_rn(s) : 0.0f;
        float4 v = out4[i];
        v.x *= inv; v.y *= inv; v.z *= inv; v.w *= inv;
        out4[i] = v;
    } else {
        int e = i - n4;
        int T = E_KG + E_UI;
        if (e >= T) return;
        float* att_out = out + (long long)(N_ENT + N_USR) * DD;
        float* w1_out  = att_out + E_UI;
        if (e < E_KG) {
            int head = eidx[e];
            w1_out[e] = g_score[e] * __frcp_rn(g_ssum[head]);
        } else {
            int j = e - E_KG;
            int u = uidx[j];
            att_out[j] = g_score[e] * __frcp_rn(g_ssum[N_ENT + u]);
        }
    }
}

// ---------------------------------------------------------------------------
extern "C" void kernel_launch(void* const* d_in, const int* in_sizes, int n_in,
                              void* d_out, int out_size)
{
    const float4* ent4   = (const float4*)d_in[0];
    const float4* usr4   = (const float4*)d_in[1];
    const float4* inter4 = (const float4*)d_in[2];
    const float4* rel4   = (const float4*)d_in[3];
    const int* eidx  = (const int*)d_in[4];
    const int* etype = (const int*)d_in[5];
    const int* uidx  = (const int*)d_in[6];
    const int* iidx  = (const int*)d_in[7];
    const int* itype = (const int*)d_in[8];
    float* out = (float*)d_out;

    int N_ENT = in_sizes[0] / DD;
    int N_USR = in_sizes[1] / DD;
    int E_KG  = in_sizes[5];
    int E_UI  = in_sizes[6];
    int T = E_KG + E_UI;
    int n_agg = (N_ENT + N_USR) * DD;
    int n_seg = N_ENT + N_USR;
    int n4 = n_agg / 4;

    const int B = 256;

    k_init<<<2048, B>>>((float4*)out, n4, n_seg);

    long long wide = (long long)T * 4;
    int g_wide = (int)((wide + B - 1) / B);
    k_fused<<<g_wide, B>>>(ent4, usr4, inter4, rel4,
                           eidx, etype, uidx, iidx, itype,
                           out, E_KG, E_UI, N_ENT, N_USR);

    int tail_work = n4 + T;
    k_tail<<<(tail_work + B - 1) / B, B>>>((float4*)out, n4, eidx, uidx, out,
                                           E_KG, E_UI, N_ENT, N_USR);
}